// round 16
// baseline (speedup 1.0000x reference)
#include <cuda_runtime.h>
#include <cuda_bf16.h>
#include <cstdint>

// Problem constants
#define NB   64
#define TT   1024
#define EE   256
#define HH   128
#define G3   384          // 3*H
#define GALL 768          // both directions
#define MROWS (NB*TT)     // 65536
#define BOTTLE 32

// ---------------- scratch (static device globals; no runtime alloc) ----------
__device__ float g_wcomb[GALL * EE];          // [768][256] combined W_ih (tf32-rna bits)
__device__ float g_bcomb[GALL];               // [768] combined b_ih (full f32)
__device__ float g_xc[(size_t)MROWS * EE];    // x pre-converted to tf32-rna bits
__device__ float g_gx[(size_t)MROWS * GALL];  // [65536][768] input gate preacts
__device__ float g_hsf[(size_t)MROWS * HH];   // forward hidden states  [m][u]
__device__ float g_hsb[(size_t)MROWS * HH];   // backward hidden states [m][u]

// ---------------- helpers ----------------------------------------------------
__device__ __forceinline__ float tanh_fast(float x) {
    float y;
    asm("tanh.approx.f32 %0, %1;" : "=f"(y) : "f"(x));
    return y;
}
__device__ __forceinline__ float sigm_fast(float x) {
    return fmaf(0.5f, tanh_fast(0.5f * x), 0.5f);
}
__device__ __forceinline__ float cvt_tf32_f(float f) {
    uint32_t r;
    asm("cvt.rna.tf32.f32 %0, %1;" : "=r"(r) : "f"(f));
    return __uint_as_float(r);
}
__device__ __forceinline__ void mma_tf32(float* c, const uint32_t* a, const uint32_t* b) {
    asm volatile(
        "mma.sync.aligned.m16n8k8.row.col.f32.tf32.tf32.f32 "
        "{%0,%1,%2,%3}, {%4,%5,%6,%7}, {%8,%9}, {%0,%1,%2,%3};"
        : "+f"(c[0]), "+f"(c[1]), "+f"(c[2]), "+f"(c[3])
        : "r"(a[0]), "r"(a[1]), "r"(a[2]), "r"(a[3]), "r"(b[0]), "r"(b[1]));
}
__device__ __forceinline__ uint32_t smem_u32(const void* p) {
    uint32_t a;
    asm("{ .reg .u64 t; cvta.to.shared.u64 t, %1; cvt.u32.u64 %0, t; }"
        : "=r"(a) : "l"(p));
    return a;
}
__device__ __forceinline__ void cp_async16(uint32_t s, const void* g) {
    asm volatile("cp.async.cg.shared.global [%0], [%1], 16;" :: "r"(s), "l"(g));
}
__device__ __forceinline__ void cp_commit() {
    asm volatile("cp.async.commit_group;");
}

// ---------------- kernel 0: merged prep (xc cvt + W pack + bias) --------------
#define NX4 ((size_t)MROWS * EE / 4)          // 4194304 float4s
#define PREP_TOTAL (NX4 + (size_t)GALL * EE + GALL)
__global__ void prep(const float* __restrict__ X,
                     const float* __restrict__ w_ih_f,
                     const float* __restrict__ b_ih_f,
                     const float* __restrict__ w_ih_b,
                     const float* __restrict__ b_ih_b) {
    size_t gid = (size_t)blockIdx.x * 256 + threadIdx.x;
    if (gid < NX4) {
        float4 v = reinterpret_cast<const float4*>(X)[gid];
        float4 o = {cvt_tf32_f(v.x), cvt_tf32_f(v.y),
                    cvt_tf32_f(v.z), cvt_tf32_f(v.w)};
        reinterpret_cast<float4*>(g_xc)[gid] = o;
    } else {
        size_t j = gid - NX4;
        if (j < (size_t)GALL * EE) {
            int g = (int)(j / EE);
            float v = (g < G3) ? w_ih_f[j] : w_ih_b[j - (size_t)G3 * EE];
            g_wcomb[j] = cvt_tf32_f(v);
        } else if (j < (size_t)GALL * EE + GALL) {
            int i = (int)(j - (size_t)GALL * EE);
            g_bcomb[i] = (i < G3) ? b_ih_f[i] : b_ih_b[i - G3];
        }
    }
}

// ---------------- kernel 1: gx GEMM, tf32 mma + cp.async (R6, BK=16) ----------
#define GBM 128
#define GBN 128
#define GBK 16
#define TSTR 20
#define NK_ITERS (EE / GBK)   // 16
__global__ __launch_bounds__(256, 2) void gemm_gx_mma(void) {
    __shared__ __align__(16) float As[2][GBM][TSTR];
    __shared__ __align__(16) float Bs[2][GBN][TSTR];

    const int tid = threadIdx.x;
    const int lane = tid & 31;
    const int warp = tid >> 5;
    const int wm = warp & 3;
    const int wn = warp >> 2;
    const int m0 = blockIdx.x * GBM;
    const int n0 = blockIdx.y * GBN;

    const int lr = tid >> 1;
    const int lc = (tid & 1) * 2;

    float c[2][8][4];
#pragma unroll
    for (int mt = 0; mt < 2; mt++)
#pragma unroll
        for (int nt = 0; nt < 8; nt++)
#pragma unroll
            for (int q = 0; q < 4; q++) c[mt][nt][q] = 0.f;

    const float* gA = g_xc + (size_t)m0 * EE;
    const float* gB = g_wcomb + (size_t)n0 * EE;

    auto issue = [&](int it, int s) {
        const int k0 = it * GBK;
#pragma unroll
        for (int cc = 0; cc < 2; cc++) {
            uint32_t sa = smem_u32(&As[s][lr][(lc + cc) * 4]);
            cp_async16(sa, gA + (size_t)lr * EE + k0 + (lc + cc) * 4);
        }
#pragma unroll
        for (int cc = 0; cc < 2; cc++) {
            uint32_t sb = smem_u32(&Bs[s][lr][(lc + cc) * 4]);
            cp_async16(sb, gB + (size_t)lr * EE + k0 + (lc + cc) * 4);
        }
    };

    issue(0, 0);
    cp_commit();

    for (int it = 0; it < NK_ITERS; it++) {
        const int s = it & 1;
        if (it + 1 < NK_ITERS) {
            issue(it + 1, s ^ 1);
            cp_commit();
            asm volatile("cp.async.wait_group 1;");
        } else {
            asm volatile("cp.async.wait_group 0;");
        }
        __syncthreads();

#pragma unroll
        for (int kt = 0; kt < 2; kt++) {
            const int kc = kt * 8 + (lane & 3);
            uint32_t a[2][4];
            uint32_t b[8][2];
#pragma unroll
            for (int mt = 0; mt < 2; mt++) {
                int m = wm * 32 + mt * 16 + (lane >> 2);
                a[mt][0] = __float_as_uint(As[s][m][kc]);
                a[mt][1] = __float_as_uint(As[s][m + 8][kc]);
                a[mt][2] = __float_as_uint(As[s][m][kc + 4]);
                a[mt][3] = __float_as_uint(As[s][m + 8][kc + 4]);
            }
#pragma unroll
            for (int nt = 0; nt < 8; nt++) {
                int n = wn * 64 + nt * 8 + (lane >> 2);
                b[nt][0] = __float_as_uint(Bs[s][n][kc]);
                b[nt][1] = __float_as_uint(Bs[s][n][kc + 4]);
            }
#pragma unroll
            for (int mt = 0; mt < 2; mt++)
#pragma unroll
                for (int nt = 0; nt < 8; nt++) mma_tf32(c[mt][nt], a[mt], b[nt]);
        }
        __syncthreads();
    }

#pragma unroll
    for (int mt = 0; mt < 2; mt++) {
        int m = m0 + wm * 32 + mt * 16 + (lane >> 2);
#pragma unroll
        for (int nt = 0; nt < 8; nt++) {
            int g = n0 + wn * 64 + nt * 8 + (lane & 3) * 2;
            float b0v = g_bcomb[g];
            float b1v = g_bcomb[g + 1];
            float2 o0 = {c[mt][nt][0] + b0v, c[mt][nt][1] + b1v};
            float2 o1 = {c[mt][nt][2] + b0v, c[mt][nt][3] + b1v};
            *reinterpret_cast<float2*>(g_gx + (size_t)m * GALL + g) = o0;
            *reinterpret_cast<float2*>(g_gx + (size_t)(m + 8) * GALL + g) = o1;
        }
    }
}

// ---------------- kernel 2: GRU scan (tanh.approx + shortened gate chain) -----
__global__ __launch_bounds__(512, 1) void gru_scan(
    const float* __restrict__ Whh_f, const float* __restrict__ bhh_f,
    const float* __restrict__ Whh_b, const float* __restrict__ bhh_b) {
    __shared__ __align__(16) float sh_h[HH];
    __shared__ __align__(16) float sp[4][3][HH];

    const int tid = threadIdx.x;
    const int u = tid & 127;
    const int jb = tid >> 7;          // 0..3
    const int blk = blockIdx.x;       // 0..127
    const int n = blk & 63;
    const int dir = blk >> 6;

    const float* Whh = dir ? Whh_b : Whh_f;
    const float* bhh = dir ? bhh_b : bhh_f;
    float* hs_out = dir ? g_hsb : g_hsf;
    const float* gx = g_gx + (size_t)n * TT * GALL + dir * G3;

    float wr[32], wz[32], wn[32];
#pragma unroll
    for (int q = 0; q < 32; q++) {
        int j = jb * 32 + q;
        wr[q] = Whh[(size_t)u * HH + j];
        wz[q] = Whh[(size_t)(HH + u) * HH + j];
        wn[q] = Whh[(size_t)(2 * HH + u) * HH + j];
    }
    float bhr = 0.f, bhz = 0.f, bhn = 0.f, hold = 0.f;
    if (jb == 0) {
        bhr = bhh[u];
        bhz = bhh[HH + u];
        bhn = bhh[2 * HH + u];
        sh_h[u] = 0.f;
    }
    __syncthreads();

    int t = dir ? (TT - 1) : 0;
    const int dt = dir ? -1 : 1;

    for (int s = 0; s < TT; s++, t += dt) {
        float gxr = 0.f, gxz = 0.f, gxn = 0.f;
        if (jb == 0) {
            const float* gxt = gx + (size_t)t * GALL;
            gxr = __ldcs(gxt + u);
            gxz = __ldcs(gxt + HH + u);
            gxn = __ldcs(gxt + 2 * HH + u);
        }

        float ar = 0.f, az = 0.f, an = 0.f;
        const float4* h4 = reinterpret_cast<const float4*>(sh_h + jb * 32);
#pragma unroll
        for (int q4 = 0; q4 < 8; q4++) {
            float4 hv = h4[q4];
            ar += wr[q4 * 4 + 0] * hv.x; az += wz[q4 * 4 + 0] * hv.x; an += wn[q4 * 4 + 0] * hv.x;
            ar += wr[q4 * 4 + 1] * hv.y; az += wz[q4 * 4 + 1] * hv.y; an += wn[q4 * 4 + 1] * hv.y;
            ar += wr[q4 * 4 + 2] * hv.z; az += wz[q4 * 4 + 2] * hv.z; an += wn[q4 * 4 + 2] * hv.z;
            ar += wr[q4 * 4 + 3] * hv.w; az += wz[q4 * 4 + 3] * hv.w; an += wn[q4 * 4 + 3] * hv.w;
        }
        sp[jb][0][u] = ar;
        sp[jb][1][u] = az;
        sp[jb][2][u] = an;
        __syncthreads();

        if (jb == 0) {
            float ghr = sp[0][0][u] + sp[1][0][u] + sp[2][0][u] + sp[3][0][u] + bhr;
            float ghz = sp[0][1][u] + sp[1][1][u] + sp[2][1][u] + sp[3][1][u] + bhz;
            float ghn = sp[0][2][u] + sp[1][2][u] + sp[2][2][u] + sp[3][2][u] + bhn;
            float r = sigm_fast(gxr + ghr);
            float nn = tanh_fast(fmaf(r, ghn, gxn));
            // hnew = (1-z)*nn + z*hold, z = 0.5*tz+0.5  ->  (nn+d) + tz*d,
            // d = 0.5*(hold - nn)  — one fewer FMA on the serial chain
            float tz = tanh_fast(0.5f * (gxz + ghz));
            float d = 0.5f * (hold - nn);
            float hnew = fmaf(tz, d, nn + d);
            hold = hnew;
            sh_h[u] = hnew;
            hs_out[((size_t)n * TT + t) * HH + u] = hnew;
        }
        __syncthreads();
    }
}

// ---------------- kernel 3: output projection (R14 256-thread, proven) --------
__global__ __launch_bounds__(256) void proj_kernel(
    const float* __restrict__ wo, const float* __restrict__ bo,
    float* __restrict__ out) {
    __shared__ float hch[256][33];
    __shared__ float wch[32][BOTTLE];

    const int tid = threadIdx.x;
    const int m0 = blockIdx.x * 256;

    float acc[BOTTLE];
#pragma unroll
    for (int b = 0; b < BOTTLE; b++) acc[b] = __ldg(bo + b);

    for (int ch = 0; ch < 8; ch++) {
        const int c0 = ch * 32;
        const float* src = (c0 < HH) ? g_hsf : g_hsb;
        const int ccol0 = (c0 < HH) ? c0 : (c0 - HH);

#pragma unroll
        for (int l = 0; l < 8; l++) {
            int idx = tid + l * 256;
            int r = idx >> 3;
            int f4i = idx & 7;
            float4 v = *reinterpret_cast<const float4*>(
                src + (size_t)(m0 + r) * HH + ccol0 + f4i * 4);
            hch[r][f4i * 4 + 0] = v.x;
            hch[r][f4i * 4 + 1] = v.y;
            hch[r][f4i * 4 + 2] = v.z;
            hch[r][f4i * 4 + 3] = v.w;
        }
        for (int i = tid; i < 32 * BOTTLE; i += 256) {
            int cc = i >> 5;
            int b = i & 31;
            wch[cc][b] = wo[(size_t)b * EE + c0 + cc];
        }
        __syncthreads();

#pragma unroll 8
        for (int cc = 0; cc < 32; cc++) {
            float v = hch[tid][cc];
            const float4* w4 = reinterpret_cast<const float4*>(wch[cc]);
#pragma unroll
            for (int b4 = 0; b4 < 8; b4++) {
                float4 wv = w4[b4];
                acc[b4 * 4 + 0] += v * wv.x;
                acc[b4 * 4 + 1] += v * wv.y;
                acc[b4 * 4 + 2] += v * wv.z;
                acc[b4 * 4 + 3] += v * wv.w;
            }
        }
        __syncthreads();
    }

    float4* dst = reinterpret_cast<float4*>(out + (size_t)(m0 + tid) * BOTTLE);
#pragma unroll
    for (int b4 = 0; b4 < 8; b4++) {
        float4 o = {acc[b4 * 4 + 0], acc[b4 * 4 + 1],
                    acc[b4 * 4 + 2], acc[b4 * 4 + 3]};
        dst[b4] = o;
    }
}

// ---------------- launch ------------------------------------------------------
extern "C" void kernel_launch(void* const* d_in, const int* in_sizes, int n_in,
                              void* d_out, int out_size) {
    const float* x      = (const float*)d_in[0];
    const float* w_ih_f = (const float*)d_in[1];
    const float* w_hh_f = (const float*)d_in[2];
    const float* b_ih_f = (const float*)d_in[3];
    const float* b_hh_f = (const float*)d_in[4];
    const float* w_ih_b = (const float*)d_in[5];
    const float* w_hh_b = (const float*)d_in[6];
    const float* b_ih_b = (const float*)d_in[7];
    const float* b_hh_b = (const float*)d_in[8];
    const float* w_out  = (const float*)d_in[9];
    const float* b_out  = (const float*)d_in[10];
    float* out = (float*)d_out;

    const int prep_blocks = (int)((PREP_TOTAL + 255) / 256);
    prep<<<prep_blocks, 256>>>(x, w_ih_f, b_ih_f, w_ih_b, b_ih_b);
    gemm_gx_mma<<<dim3(MROWS / GBM, GALL / GBN), 256>>>();
    gru_scan<<<128, 512>>>(w_hh_f, b_hh_f, w_hh_b, b_hh_b);
    proj_kernel<<<MROWS / 256, 256>>>(w_out, b_out, out);
}

// round 17
// speedup vs baseline: 1.3997x; 1.3997x over previous
#include <cuda_runtime.h>
#include <cuda_bf16.h>
#include <cstdint>

// Problem constants
#define NB   64
#define TT   1024
#define EE   256
#define HH   128
#define G3   384          // 3*H
#define GALL 768          // both directions
#define MROWS (NB*TT)     // 65536
#define BOTTLE 32

// ---------------- scratch (static device globals; no runtime alloc) ----------
__device__ float g_wcomb[GALL * EE];          // [768][256] combined W_ih (tf32-rna bits)
__device__ float g_bcomb[GALL];               // [768] combined b_ih (full f32)
__device__ float g_xc[(size_t)MROWS * EE];    // x pre-converted to tf32-rna bits
__device__ float g_gx[(size_t)MROWS * GALL];  // [65536][768] input gate preacts
__device__ float g_hsf[(size_t)MROWS * HH];   // forward hidden states  [m][u]
__device__ float g_hsb[(size_t)MROWS * HH];   // backward hidden states [m][u]

// ---------------- helpers ----------------------------------------------------
__device__ __forceinline__ float tanh_fast(float x) {
    float y;
    asm("tanh.approx.f32 %0, %1;" : "=f"(y) : "f"(x));
    return y;
}
__device__ __forceinline__ float sigm_fast(float x) {
    return fmaf(0.5f, tanh_fast(0.5f * x), 0.5f);
}
__device__ __forceinline__ float cvt_tf32_f(float f) {
    uint32_t r;
    asm("cvt.rna.tf32.f32 %0, %1;" : "=r"(r) : "f"(f));
    return __uint_as_float(r);
}
__device__ __forceinline__ void mma_tf32(float* c, const uint32_t* a, const uint32_t* b) {
    asm volatile(
        "mma.sync.aligned.m16n8k8.row.col.f32.tf32.tf32.f32 "
        "{%0,%1,%2,%3}, {%4,%5,%6,%7}, {%8,%9}, {%0,%1,%2,%3};"
        : "+f"(c[0]), "+f"(c[1]), "+f"(c[2]), "+f"(c[3])
        : "r"(a[0]), "r"(a[1]), "r"(a[2]), "r"(a[3]), "r"(b[0]), "r"(b[1]));
}
__device__ __forceinline__ uint32_t smem_u32(const void* p) {
    uint32_t a;
    asm("{ .reg .u64 t; cvta.to.shared.u64 t, %1; cvt.u32.u64 %0, t; }"
        : "=r"(a) : "l"(p));
    return a;
}
__device__ __forceinline__ void cp_async16(uint32_t s, const void* g) {
    asm volatile("cp.async.cg.shared.global [%0], [%1], 16;" :: "r"(s), "l"(g));
}
__device__ __forceinline__ void cp_commit() {
    asm volatile("cp.async.commit_group;");
}

// ---------------- kernel 0: merged prep (xc cvt + W pack + bias) --------------
#define NX4 ((size_t)MROWS * EE / 4)          // 4194304 float4s
#define PREP_TOTAL (NX4 + (size_t)GALL * EE + GALL)
__global__ void prep(const float* __restrict__ X,
                     const float* __restrict__ w_ih_f,
                     const float* __restrict__ b_ih_f,
                     const float* __restrict__ w_ih_b,
                     const float* __restrict__ b_ih_b) {
    size_t gid = (size_t)blockIdx.x * 256 + threadIdx.x;
    if (gid < NX4) {
        float4 v = reinterpret_cast<const float4*>(X)[gid];
        float4 o = {cvt_tf32_f(v.x), cvt_tf32_f(v.y),
                    cvt_tf32_f(v.z), cvt_tf32_f(v.w)};
        reinterpret_cast<float4*>(g_xc)[gid] = o;
    } else {
        size_t j = gid - NX4;
        if (j < (size_t)GALL * EE) {
            int g = (int)(j / EE);
            float v = (g < G3) ? w_ih_f[j] : w_ih_b[j - (size_t)G3 * EE];
            g_wcomb[j] = cvt_tf32_f(v);
        } else if (j < (size_t)GALL * EE + GALL) {
            int i = (int)(j - (size_t)GALL * EE);
            g_bcomb[i] = (i < G3) ? b_ih_f[i] : b_ih_b[i - G3];
        }
    }
}

// ---------------- kernel 1: gx GEMM, tf32 mma + cp.async (R6, BK=16) ----------
#define GBM 128
#define GBN 128
#define GBK 16
#define TSTR 20
#define NK_ITERS (EE / GBK)   // 16
__global__ __launch_bounds__(256, 2) void gemm_gx_mma(void) {
    __shared__ __align__(16) float As[2][GBM][TSTR];
    __shared__ __align__(16) float Bs[2][GBN][TSTR];

    const int tid = threadIdx.x;
    const int lane = tid & 31;
    const int warp = tid >> 5;
    const int wm = warp & 3;
    const int wn = warp >> 2;
    const int m0 = blockIdx.x * GBM;
    const int n0 = blockIdx.y * GBN;

    const int lr = tid >> 1;
    const int lc = (tid & 1) * 2;

    float c[2][8][4];
#pragma unroll
    for (int mt = 0; mt < 2; mt++)
#pragma unroll
        for (int nt = 0; nt < 8; nt++)
#pragma unroll
            for (int q = 0; q < 4; q++) c[mt][nt][q] = 0.f;

    const float* gA = g_xc + (size_t)m0 * EE;
    const float* gB = g_wcomb + (size_t)n0 * EE;

    auto issue = [&](int it, int s) {
        const int k0 = it * GBK;
#pragma unroll
        for (int cc = 0; cc < 2; cc++) {
            uint32_t sa = smem_u32(&As[s][lr][(lc + cc) * 4]);
            cp_async16(sa, gA + (size_t)lr * EE + k0 + (lc + cc) * 4);
        }
#pragma unroll
        for (int cc = 0; cc < 2; cc++) {
            uint32_t sb = smem_u32(&Bs[s][lr][(lc + cc) * 4]);
            cp_async16(sb, gB + (size_t)lr * EE + k0 + (lc + cc) * 4);
        }
    };

    issue(0, 0);
    cp_commit();

    for (int it = 0; it < NK_ITERS; it++) {
        const int s = it & 1;
        if (it + 1 < NK_ITERS) {
            issue(it + 1, s ^ 1);
            cp_commit();
            asm volatile("cp.async.wait_group 1;");
        } else {
            asm volatile("cp.async.wait_group 0;");
        }
        __syncthreads();

#pragma unroll
        for (int kt = 0; kt < 2; kt++) {
            const int kc = kt * 8 + (lane & 3);
            uint32_t a[2][4];
            uint32_t b[8][2];
#pragma unroll
            for (int mt = 0; mt < 2; mt++) {
                int m = wm * 32 + mt * 16 + (lane >> 2);
                a[mt][0] = __float_as_uint(As[s][m][kc]);
                a[mt][1] = __float_as_uint(As[s][m + 8][kc]);
                a[mt][2] = __float_as_uint(As[s][m][kc + 4]);
                a[mt][3] = __float_as_uint(As[s][m + 8][kc + 4]);
            }
#pragma unroll
            for (int nt = 0; nt < 8; nt++) {
                int n = wn * 64 + nt * 8 + (lane >> 2);
                b[nt][0] = __float_as_uint(Bs[s][n][kc]);
                b[nt][1] = __float_as_uint(Bs[s][n][kc + 4]);
            }
#pragma unroll
            for (int mt = 0; mt < 2; mt++)
#pragma unroll
                for (int nt = 0; nt < 8; nt++) mma_tf32(c[mt][nt], a[mt], b[nt]);
        }
        __syncthreads();
    }

#pragma unroll
    for (int mt = 0; mt < 2; mt++) {
        int m = m0 + wm * 32 + mt * 16 + (lane >> 2);
#pragma unroll
        for (int nt = 0; nt < 8; nt++) {
            int g = n0 + wn * 64 + nt * 8 + (lane & 3) * 2;
            float b0v = g_bcomb[g];
            float b1v = g_bcomb[g + 1];
            float2 o0 = {c[mt][nt][0] + b0v, c[mt][nt][1] + b1v};
            float2 o1 = {c[mt][nt][2] + b0v, c[mt][nt][3] + b1v};
            *reinterpret_cast<float2*>(g_gx + (size_t)m * GALL + g) = o0;
            *reinterpret_cast<float2*>(g_gx + (size_t)(m + 8) * GALL + g) = o1;
        }
    }
}

// ---------------- kernel 2: GRU scan (tanh.approx + shortened gate chain) -----
__global__ __launch_bounds__(512, 1) void gru_scan(
    const float* __restrict__ Whh_f, const float* __restrict__ bhh_f,
    const float* __restrict__ Whh_b, const float* __restrict__ bhh_b) {
    __shared__ __align__(16) float sh_h[HH];
    __shared__ __align__(16) float sp[4][3][HH];

    const int tid = threadIdx.x;
    const int u = tid & 127;
    const int jb = tid >> 7;          // 0..3
    const int blk = blockIdx.x;       // 0..127
    const int n = blk & 63;
    const int dir = blk >> 6;

    const float* Whh = dir ? Whh_b : Whh_f;
    const float* bhh = dir ? bhh_b : bhh_f;
    float* hs_out = dir ? g_hsb : g_hsf;
    const float* gx = g_gx + (size_t)n * TT * GALL + dir * G3;

    float wr[32], wz[32], wn[32];
#pragma unroll
    for (int q = 0; q < 32; q++) {
        int j = jb * 32 + q;
        wr[q] = Whh[(size_t)u * HH + j];
        wz[q] = Whh[(size_t)(HH + u) * HH + j];
        wn[q] = Whh[(size_t)(2 * HH + u) * HH + j];
    }
    float bhr = 0.f, bhz = 0.f, bhn = 0.f, hold = 0.f;
    if (jb == 0) {
        bhr = bhh[u];
        bhz = bhh[HH + u];
        bhn = bhh[2 * HH + u];
        sh_h[u] = 0.f;
    }
    __syncthreads();

    int t = dir ? (TT - 1) : 0;
    const int dt = dir ? -1 : 1;

    for (int s = 0; s < TT; s++, t += dt) {
        float gxr = 0.f, gxz = 0.f, gxn = 0.f;
        if (jb == 0) {
            const float* gxt = gx + (size_t)t * GALL;
            gxr = __ldcs(gxt + u);
            gxz = __ldcs(gxt + HH + u);
            gxn = __ldcs(gxt + 2 * HH + u);
        }

        float ar = 0.f, az = 0.f, an = 0.f;
        const float4* h4 = reinterpret_cast<const float4*>(sh_h + jb * 32);
#pragma unroll
        for (int q4 = 0; q4 < 8; q4++) {
            float4 hv = h4[q4];
            ar += wr[q4 * 4 + 0] * hv.x; az += wz[q4 * 4 + 0] * hv.x; an += wn[q4 * 4 + 0] * hv.x;
            ar += wr[q4 * 4 + 1] * hv.y; az += wz[q4 * 4 + 1] * hv.y; an += wn[q4 * 4 + 1] * hv.y;
            ar += wr[q4 * 4 + 2] * hv.z; az += wz[q4 * 4 + 2] * hv.z; an += wn[q4 * 4 + 2] * hv.z;
            ar += wr[q4 * 4 + 3] * hv.w; az += wz[q4 * 4 + 3] * hv.w; an += wn[q4 * 4 + 3] * hv.w;
        }
        sp[jb][0][u] = ar;
        sp[jb][1][u] = az;
        sp[jb][2][u] = an;
        __syncthreads();

        if (jb == 0) {
            float ghr = sp[0][0][u] + sp[1][0][u] + sp[2][0][u] + sp[3][0][u] + bhr;
            float ghz = sp[0][1][u] + sp[1][1][u] + sp[2][1][u] + sp[3][1][u] + bhz;
            float ghn = sp[0][2][u] + sp[1][2][u] + sp[2][2][u] + sp[3][2][u] + bhn;
            float r = sigm_fast(gxr + ghr);
            float nn = tanh_fast(fmaf(r, ghn, gxn));
            // hnew = (1-z)*nn + z*hold, z = 0.5*tz+0.5  ->  (nn+d) + tz*d,
            // d = 0.5*(hold - nn)  — one fewer FMA on the serial chain
            float tz = tanh_fast(0.5f * (gxz + ghz));
            float d = 0.5f * (hold - nn);
            float hnew = fmaf(tz, d, nn + d);
            hold = hnew;
            sh_h[u] = hnew;
            hs_out[((size_t)n * TT + t) * HH + u] = hnew;
        }
        __syncthreads();
    }
}

// ---------------- kernel 3: output projection (R14 256-thread, proven) --------
__global__ __launch_bounds__(256) void proj_kernel(
    const float* __restrict__ wo, const float* __restrict__ bo,
    float* __restrict__ out) {
    __shared__ float hch[256][33];
    __shared__ float wch[32][BOTTLE];

    const int tid = threadIdx.x;
    const int m0 = blockIdx.x * 256;

    float acc[BOTTLE];
#pragma unroll
    for (int b = 0; b < BOTTLE; b++) acc[b] = __ldg(bo + b);

    for (int ch = 0; ch < 8; ch++) {
        const int c0 = ch * 32;
        const float* src = (c0 < HH) ? g_hsf : g_hsb;
        const int ccol0 = (c0 < HH) ? c0 : (c0 - HH);

#pragma unroll
        for (int l = 0; l < 8; l++) {
            int idx = tid + l * 256;
            int r = idx >> 3;
            int f4i = idx & 7;
            float4 v = *reinterpret_cast<const float4*>(
                src + (size_t)(m0 + r) * HH + ccol0 + f4i * 4);
            hch[r][f4i * 4 + 0] = v.x;
            hch[r][f4i * 4 + 1] = v.y;
            hch[r][f4i * 4 + 2] = v.z;
            hch[r][f4i * 4 + 3] = v.w;
        }
        for (int i = tid; i < 32 * BOTTLE; i += 256) {
            int cc = i >> 5;
            int b = i & 31;
            wch[cc][b] = wo[(size_t)b * EE + c0 + cc];
        }
        __syncthreads();

#pragma unroll 8
        for (int cc = 0; cc < 32; cc++) {
            float v = hch[tid][cc];
            const float4* w4 = reinterpret_cast<const float4*>(wch[cc]);
#pragma unroll
            for (int b4 = 0; b4 < 8; b4++) {
                float4 wv = w4[b4];
                acc[b4 * 4 + 0] += v * wv.x;
                acc[b4 * 4 + 1] += v * wv.y;
                acc[b4 * 4 + 2] += v * wv.z;
                acc[b4 * 4 + 3] += v * wv.w;
            }
        }
        __syncthreads();
    }

    float4* dst = reinterpret_cast<float4*>(out + (size_t)(m0 + tid) * BOTTLE);
#pragma unroll
    for (int b4 = 0; b4 < 8; b4++) {
        float4 o = {acc[b4 * 4 + 0], acc[b4 * 4 + 1],
                    acc[b4 * 4 + 2], acc[b4 * 4 + 3]};
        dst[b4] = o;
    }
}

// ---------------- launch ------------------------------------------------------
extern "C" void kernel_launch(void* const* d_in, const int* in_sizes, int n_in,
                              void* d_out, int out_size) {
    const float* x      = (const float*)d_in[0];
    const float* w_ih_f = (const float*)d_in[1];
    const float* w_hh_f = (const float*)d_in[2];
    const float* b_ih_f = (const float*)d_in[3];
    const float* b_hh_f = (const float*)d_in[4];
    const float* w_ih_b = (const float*)d_in[5];
    const float* w_hh_b = (const float*)d_in[6];
    const float* b_ih_b = (const float*)d_in[7];
    const float* b_hh_b = (const float*)d_in[8];
    const float* w_out  = (const float*)d_in[9];
    const float* b_out  = (const float*)d_in[10];
    float* out = (float*)d_out;

    const int prep_blocks = (int)((PREP_TOTAL + 255) / 256);
    prep<<<prep_blocks, 256>>>(x, w_ih_f, b_ih_f, w_ih_b, b_ih_b);
    gemm_gx_mma<<<dim3(MROWS / GBM, GALL / GBN), 256>>>();
    gru_scan<<<128, 512>>>(w_hh_f, b_hh_f, w_hh_b, b_hh_b);
    proj_kernel<<<MROWS / 256, 256>>>(w_out, b_out, out);
}